// round 5
// baseline (speedup 1.0000x reference)
#include <cuda_runtime.h>
#include <cuda_bf16.h>
#include <cstdint>

// RMAC max-pool over 14 fixed regions of a (64, 37, 37, 512) fp32 tensor.
// Single fused kernel: per-slice partial maxes + last-block-done combine.
// Regions for W=H=37, L=3:
//   r0 : (0,0,37,37)
//   r1-4 : 24x24 at (x,y) in {0,13}^2   (y outer, x inner)
//   r5-13: 18x18 at (x,y) in {0,9,19}^2 (y outer, x inner)
// Column intervals: m0=[0,37) m1=[0,24) m2=[13,37) m3=[0,18) m4=[9,27) m5=[19,37)
// built from disjoint segments S1=[0,9) S2=[9,13) S3=[13,18) S4=[18,19)
//                              S5=[19,24) S6=[24,27) S7=[27,37)

#define BATCH   64
#define HH      37
#define WW      37
#define NCH     512
#define NREG    14
#define NSLICE  4
#define CPB     128              // channels per block (= threads per block)
#define NCHUNK  (NCH / CPB)      // 4
#define NGRP    (BATCH * NCHUNK) // 256 combine groups

#define NEG_INF __int_as_float(0xff800000)

// Per-slice partial region maxes: [slice][b][region][channel]  (~7.3 MB)
__device__ float g_part[NSLICE][BATCH][NREG][NCH];
// Completion tickets per (b, chunk) group. Zero-initialized at module load;
// the finishing block resets its counter to 0, so every launch (and every
// graph replay) starts from zeros. Deterministic.
__device__ int g_cnt[NGRP];

__global__ __launch_bounds__(CPB) void rmac_fused_kernel(const float* __restrict__ x,
                                                         float* __restrict__ out) {
    const int bid   = blockIdx.x;            // 0 .. 1023
    const int s     = bid & (NSLICE - 1);    // row slice
    const int chunk = (bid >> 2) & (NCHUNK - 1);
    const int b     = bid >> 4;              // batch
    const int grp   = bid >> 2;              // (b, chunk) group
    const int c     = chunk * CPB + threadIdx.x;

    const int h0 = (s * HH) / NSLICE;
    const int h1 = ((s + 1) * HH) / NSLICE;

    float acc[NREG];
#pragma unroll
    for (int r = 0; r < NREG; ++r) acc[r] = NEG_INF;

    const float* base = x + ((size_t)b * HH * WW) * NCH + c;

    for (int h = h0; h < h1; ++h) {
        const float* row = base + (size_t)h * WW * NCH;
#define LDW(w) __ldcs(row + (w) * NCH)

        // 7 disjoint segment maxes (30 fmax, 37 streaming LDG)
        float s1 = LDW(0);
#pragma unroll
        for (int w = 1; w < 9; ++w)   s1 = fmaxf(s1, LDW(w));
        float s2 = LDW(9);
#pragma unroll
        for (int w = 10; w < 13; ++w) s2 = fmaxf(s2, LDW(w));
        float s3 = LDW(13);
#pragma unroll
        for (int w = 14; w < 18; ++w) s3 = fmaxf(s3, LDW(w));
        float s4 = LDW(18);
        float s5 = LDW(19);
#pragma unroll
        for (int w = 20; w < 24; ++w) s5 = fmaxf(s5, LDW(w));
        float s6 = LDW(24);
#pragma unroll
        for (int w = 25; w < 27; ++w) s6 = fmaxf(s6, LDW(w));
        float s7 = LDW(27);
#pragma unroll
        for (int w = 28; w < 37; ++w) s7 = fmaxf(s7, LDW(w));
#undef LDW

        // Combine segments into the 6 column-interval maxes (13 fmax)
        const float m3  = fmaxf(fmaxf(s1, s2), s3);        // [0,18)
        const float m1  = fmaxf(fmaxf(m3, s4), s5);        // [0,24)
        const float m0  = fmaxf(fmaxf(m1, s6), s7);        // [0,37)
        const float s56 = fmaxf(s5, s6);
        const float m5  = fmaxf(s56, s7);                  // [19,37)
        const float m4  = fmaxf(fmaxf(fmaxf(s2, s3), s4), s56); // [9,27)
        const float m2  = fmaxf(fmaxf(s3, s4), m5);        // [13,37)

        // Fold row maxes into region accumulators (runtime predicates on h).
        acc[0] = fmaxf(acc[0], m0);
        const bool pA = (h < 24);               // rows [0,24)
        const bool pB = (h >= 13);              // rows [13,37)
        const bool pC = (h < 18);               // rows [0,18)
        const bool pD = (h >= 9 && h < 27);     // rows [9,27)
        const bool pE = (h >= 19);              // rows [19,37)
        if (pA) { acc[1]  = fmaxf(acc[1],  m1); acc[2]  = fmaxf(acc[2],  m2); }
        if (pB) { acc[3]  = fmaxf(acc[3],  m1); acc[4]  = fmaxf(acc[4],  m2); }
        if (pC) { acc[5]  = fmaxf(acc[5],  m3); acc[6]  = fmaxf(acc[6],  m4); acc[7]  = fmaxf(acc[7],  m5); }
        if (pD) { acc[8]  = fmaxf(acc[8],  m3); acc[9]  = fmaxf(acc[9],  m4); acc[10] = fmaxf(acc[10], m5); }
        if (pE) { acc[11] = fmaxf(acc[11], m3); acc[12] = fmaxf(acc[12], m4); acc[13] = fmaxf(acc[13], m5); }
    }

    // Publish this slice's partials.
#pragma unroll
    for (int r = 0; r < NREG; ++r)
        g_part[s][b][r][c] = acc[r];

    // Make stores visible device-wide, then take a ticket.
    __threadfence();
    __syncthreads();

    __shared__ int s_ticket;
    if (threadIdx.x == 0)
        s_ticket = atomicAdd(&g_cnt[grp], 1);
    __syncthreads();

    if (s_ticket == NSLICE - 1) {
        // Last block of this (b, chunk) group: all peers fenced their stores
        // before their atomicAdd, so all 4 slice partials are visible.
        __threadfence();

        float* o = out + ((size_t)b * NREG) * NCH + c;
#pragma unroll
        for (int r = 0; r < NREG; ++r) {
            float v = g_part[0][b][r][c];
#pragma unroll
            for (int ss = 1; ss < NSLICE; ++ss)
                v = fmaxf(v, g_part[ss][b][r][c]);
            o[r * NCH] = v;
        }

        // Self-clean for the next launch / graph replay.
        __threadfence();
        __syncthreads();
        if (threadIdx.x == 0)
            g_cnt[grp] = 0;
    }
}

extern "C" void kernel_launch(void* const* d_in, const int* in_sizes, int n_in,
                              void* d_out, int out_size) {
    const float* x = (const float*)d_in[0];
    float* out = (float*)d_out;

    rmac_fused_kernel<<<BATCH * NCHUNK * NSLICE, CPB>>>(x, out);
}

// round 6
// speedup vs baseline: 1.3517x; 1.3517x over previous
#include <cuda_runtime.h>
#include <cuda_bf16.h>
#include <cstdint>

// RMAC max-pool over 14 fixed regions of a (64, 37, 37, 512) fp32 tensor.
// Single fused kernel: per-slice partial maxes + last-block-done combine.
// Regions for W=H=37, L=3:
//   r0 : (0,0,37,37)
//   r1-4 : 24x24 at (x,y) in {0,13}^2   (y outer, x inner)
//   r5-13: 18x18 at (x,y) in {0,9,19}^2 (y outer, x inner)
// Column intervals: m0=[0,37) m1=[0,24) m2=[13,37) m3=[0,18) m4=[9,27) m5=[19,37)
// built from disjoint segments S1=[0,9) S2=[9,13) S3=[13,18) S4=[18,19)
//                              S5=[19,24) S6=[24,27) S7=[27,37)

#define BATCH   64
#define HH      37
#define WW      37
#define NCH     512
#define NREG    14
#define NSLICE  4
#define CPB     128              // channels per block (= threads per block)
#define NCHUNK  (NCH / CPB)      // 4
#define NGRP    (BATCH * NCHUNK) // 256 combine groups

#define NEG_INF __int_as_float(0xff800000)

// Per-slice partial region maxes: [slice][b][region][channel]  (~7.3 MB)
__device__ float g_part[NSLICE][BATCH][NREG][NCH];
// Completion tickets per (b, chunk) group. Zero-initialized at module load;
// the finishing block resets its counter to 0 -> deterministic across
// launches and graph replays.
__device__ int g_cnt[NGRP];

__global__ __launch_bounds__(CPB, 8) void rmac_fused_kernel(const float* __restrict__ x,
                                                            float* __restrict__ out) {
    const int bid   = blockIdx.x;            // 0 .. 1023
    const int s     = bid & (NSLICE - 1);    // row slice
    const int chunk = (bid >> 2) & (NCHUNK - 1);
    const int b     = bid >> 4;              // batch
    const int grp   = bid >> 2;              // (b, chunk) group
    const int c     = chunk * CPB + threadIdx.x;

    const int h0 = (s * HH) / NSLICE;
    const int h1 = ((s + 1) * HH) / NSLICE;

    float acc[NREG];
#pragma unroll
    for (int r = 0; r < NREG; ++r) acc[r] = NEG_INF;

    const float* base = x + ((size_t)b * HH * WW) * NCH + c;

    for (int h = h0; h < h1; ++h) {
        const float* row = base + (size_t)h * WW * NCH;

        // Batch ALL 37 independent loads up front -> per-warp MLP = 37.
        // This is the load-latency hiding; do not let fmax consume early.
        float v[WW];
#pragma unroll
        for (int w = 0; w < WW; ++w)
            v[w] = __ldcs(row + w * NCH);     // streaming: read-once data

        // 7 disjoint segment maxes (30 fmax)
        float s1 = v[0];
#pragma unroll
        for (int w = 1; w < 9; ++w)   s1 = fmaxf(s1, v[w]);
        float s2 = v[9];
#pragma unroll
        for (int w = 10; w < 13; ++w) s2 = fmaxf(s2, v[w]);
        float s3 = v[13];
#pragma unroll
        for (int w = 14; w < 18; ++w) s3 = fmaxf(s3, v[w]);
        const float s4 = v[18];
        float s5 = v[19];
#pragma unroll
        for (int w = 20; w < 24; ++w) s5 = fmaxf(s5, v[w]);
        float s6 = v[24];
#pragma unroll
        for (int w = 25; w < 27; ++w) s6 = fmaxf(s6, v[w]);
        float s7 = v[27];
#pragma unroll
        for (int w = 28; w < 37; ++w) s7 = fmaxf(s7, v[w]);

        // Combine segments into the 6 column-interval maxes (13 fmax)
        const float m3  = fmaxf(fmaxf(s1, s2), s3);        // [0,18)
        const float m1  = fmaxf(fmaxf(m3, s4), s5);        // [0,24)
        const float m0  = fmaxf(fmaxf(m1, s6), s7);        // [0,37)
        const float s56 = fmaxf(s5, s6);
        const float m5  = fmaxf(s56, s7);                  // [19,37)
        const float m4  = fmaxf(fmaxf(fmaxf(s2, s3), s4), s56); // [9,27)
        const float m2  = fmaxf(fmaxf(s3, s4), m5);        // [13,37)

        // Fold row maxes into region accumulators (runtime predicates on h).
        acc[0] = fmaxf(acc[0], m0);
        const bool pA = (h < 24);               // rows [0,24)
        const bool pB = (h >= 13);              // rows [13,37)
        const bool pC = (h < 18);               // rows [0,18)
        const bool pD = (h >= 9 && h < 27);     // rows [9,27)
        const bool pE = (h >= 19);              // rows [19,37)
        if (pA) { acc[1]  = fmaxf(acc[1],  m1); acc[2]  = fmaxf(acc[2],  m2); }
        if (pB) { acc[3]  = fmaxf(acc[3],  m1); acc[4]  = fmaxf(acc[4],  m2); }
        if (pC) { acc[5]  = fmaxf(acc[5],  m3); acc[6]  = fmaxf(acc[6],  m4); acc[7]  = fmaxf(acc[7],  m5); }
        if (pD) { acc[8]  = fmaxf(acc[8],  m3); acc[9]  = fmaxf(acc[9],  m4); acc[10] = fmaxf(acc[10], m5); }
        if (pE) { acc[11] = fmaxf(acc[11], m3); acc[12] = fmaxf(acc[12], m4); acc[13] = fmaxf(acc[13], m5); }
    }

    // Publish this slice's partials.
#pragma unroll
    for (int r = 0; r < NREG; ++r)
        g_part[s][b][r][c] = acc[r];

    // Make stores visible device-wide, then take a ticket.
    __threadfence();
    __syncthreads();

    __shared__ int s_ticket;
    if (threadIdx.x == 0)
        s_ticket = atomicAdd(&g_cnt[grp], 1);
    __syncthreads();

    if (s_ticket == NSLICE - 1) {
        // Last block of this (b, chunk) group: all peers fenced their stores
        // before their atomicAdd, so all 4 slice partials are visible.
        __threadfence();

        float* o = out + ((size_t)b * NREG) * NCH + c;
#pragma unroll
        for (int r = 0; r < NREG; ++r) {
            float v0 = fmaxf(g_part[0][b][r][c], g_part[1][b][r][c]);
            float v1 = fmaxf(g_part[2][b][r][c], g_part[3][b][r][c]);
            o[r * NCH] = fmaxf(v0, v1);
        }

        // Self-clean for the next launch / graph replay.
        __threadfence();
        __syncthreads();
        if (threadIdx.x == 0)
            g_cnt[grp] = 0;
    }
}

extern "C" void kernel_launch(void* const* d_in, const int* in_sizes, int n_in,
                              void* d_out, int out_size) {
    const float* x = (const float*)d_in[0];
    float* out = (float*)d_out;

    rmac_fused_kernel<<<BATCH * NCHUNK * NSLICE, CPB>>>(x, out);
}